// round 12
// baseline (speedup 1.0000x reference)
#include <cuda_runtime.h>
#include <cuda_bf16.h>
#include <math.h>
#include <stdint.h>

#define NN 100000
#define NE 1000000
#define D  64

// ---------------- scratch ----------------------------------------------------
__device__ int      g_deg[NN];
__device__ int      g_off[NN];
__device__ int      g_rank[NE];
__device__ int      g_adj[NE];
__device__ float    g_h[NN * D];
__device__ float    g_meanbuf[NN * D];
__device__ unsigned g_scanpub[128];
__device__ int      g_is64;

#define SCAN_B 1024
#define SCAN_NB ((NN + SCAN_B - 1) / SCAN_B)   // 98

// ---------------- edge dtype handling ---------------------------------------
__device__ __forceinline__ int edge_at(const void* ei, int idx, int is64) {
    if (is64) return (int)((const long long*)ei)[idx];
    return ((const int*)ei)[idx];
}

// init: zero degree counters + scan flags; last block runs the dtype probe.
__global__ void k_init(const long long* __restrict__ ei) {
    int i = blockIdx.x * blockDim.x + threadIdx.x;
    if (i < NN) g_deg[i] = 0;
    if (i < SCAN_NB) g_scanpub[i] = 0u;
    if (blockIdx.x == gridDim.x - 1) {
        __shared__ int bad;
        if (threadIdx.x == 0) bad = 0;
        __syncthreads();
        for (int t = threadIdx.x; t < 2048; t += blockDim.x) {
            long long v = ei[t];
            if (v < 0 || v >= NN) bad = 1;
        }
        __syncthreads();
        if (threadIdx.x == 0) g_is64 = bad ? 0 : 1;
    }
}

// ---------------- CSR build --------------------------------------------------
// hist assigns each edge its within-bucket rank via the atomicAdd return value;
// fill then needs NO atomics at all.
#define HIST_ILP 2
__global__ void k_hist(const void* __restrict__ ei) {
    int gid = blockIdx.x * blockDim.x + threadIdx.x;
    int stride = gridDim.x * blockDim.x;
    int is64 = g_is64;
    int dst[HIST_ILP];
#pragma unroll
    for (int u = 0; u < HIST_ILP; u++) {
        int e = gid + u * stride;
        dst[u] = (e < NE) ? edge_at(ei, NE + e, is64) : -1;
    }
    int rk[HIST_ILP];
#pragma unroll
    for (int u = 0; u < HIST_ILP; u++)
        rk[u] = ((unsigned)dst[u] < NN) ? atomicAdd(&g_deg[dst[u]], 1) : -1;
#pragma unroll
    for (int u = 0; u < HIST_ILP; u++) {
        int e = gid + u * stride;
        if (rk[u] >= 0) g_rank[e] = rk[u];
    }
}

// single-pass exclusive scan with decoupled lookback.
__global__ __launch_bounds__(SCAN_B) void k_scan(void) {
    __shared__ int wsum[32];
    __shared__ int s_base;
    int tid = threadIdx.x, lane = tid & 31, w = tid >> 5;
    int i = blockIdx.x * SCAN_B + tid;
    int v = (i < NN) ? g_deg[i] : 0;
    int p = v;
#pragma unroll
    for (int st = 1; st < 32; st <<= 1) {
        int t = __shfl_up_sync(0xFFFFFFFFu, p, st);
        if (lane >= st) p += t;
    }
    if (lane == 31) wsum[w] = p;
    if (tid == 0) s_base = 0;
    __syncthreads();
    if (w == 0) {
        int s = wsum[lane];
#pragma unroll
        for (int st = 1; st < 32; st <<= 1) {
            int t = __shfl_up_sync(0xFFFFFFFFu, s, st);
            if (lane >= st) s += t;
        }
        wsum[lane] = s;
    }
    __syncthreads();
    int wbase = (w > 0) ? wsum[w - 1] : 0;
    int incl = wbase + p;
    if (tid == SCAN_B - 1)
        ((volatile unsigned*)g_scanpub)[blockIdx.x] = 0x80000000u | (unsigned)incl;
    if (tid < blockIdx.x) {
        unsigned u;
        do { u = ((volatile unsigned*)g_scanpub)[tid]; } while (!(u & 0x80000000u));
        atomicAdd(&s_base, (int)(u & 0x7FFFFFFFu));
    }
    __syncthreads();
    if (i < NN) g_off[i] = s_base + incl - v;
}

// atomic-free fill: slot = off[dst] + rank[e]
#define EDGE_ILP 4
__global__ void k_fill(const void* __restrict__ ei) {
    int gid = blockIdx.x * blockDim.x + threadIdx.x;
    int stride = gridDim.x * blockDim.x;
    int is64 = g_is64;
    int src[EDGE_ILP], dst[EDGE_ILP], rk[EDGE_ILP];
#pragma unroll
    for (int u = 0; u < EDGE_ILP; u++) {
        int e = gid + u * stride;
        if (e < NE) {
            src[u] = edge_at(ei, e, is64);
            dst[u] = edge_at(ei, NE + e, is64);
            rk[u]  = g_rank[e];
        } else { src[u] = -1; dst[u] = -1; rk[u] = 0; }
    }
    int base[EDGE_ILP];
#pragma unroll
    for (int u = 0; u < EDGE_ILP; u++)
        base[u] = ((unsigned)dst[u] < NN) ? __ldg(&g_off[dst[u]]) : -1;
#pragma unroll
    for (int u = 0; u < EDGE_ILP; u++)
        if (base[u] >= 0 && (unsigned)src[u] < NN)
            g_adj[base[u] + rk[u]] = src[u];
}

// ---------------- mean aggregation: half-warp per node, float4 --------------
__global__ void k_agg(const float* __restrict__ feat, float* __restrict__ outm) {
    int hw = (blockIdx.x * blockDim.x + threadIdx.x) >> 4;  // node id
    int c  = threadIdx.x & 15;                              // float4 lane
    if (hw >= NN) return;
    int d = g_deg[hw];
    int o = g_off[hw];
    const float4* f4 = (const float4*)feat;
    float4 a = make_float4(0.f, 0.f, 0.f, 0.f);
    int t = 0;
    for (; t + 4 <= d; t += 4) {
        int nb0 = g_adj[o + t];
        int nb1 = g_adj[o + t + 1];
        int nb2 = g_adj[o + t + 2];
        int nb3 = g_adj[o + t + 3];
        float4 v0 = f4[nb0 * 16 + c];
        float4 v1 = f4[nb1 * 16 + c];
        float4 v2 = f4[nb2 * 16 + c];
        float4 v3 = f4[nb3 * 16 + c];
        a.x += v0.x + v1.x + v2.x + v3.x;
        a.y += v0.y + v1.y + v2.y + v3.y;
        a.z += v0.z + v1.z + v2.z + v3.z;
        a.w += v0.w + v1.w + v2.w + v3.w;
    }
    for (; t < d; t++) {
        int nb = g_adj[o + t];
        float4 v = f4[nb * 16 + c];
        a.x += v.x; a.y += v.y; a.z += v.z; a.w += v.w;
    }
    float inv = 1.0f / (float)max(d, 1);
    a.x *= inv; a.y *= inv; a.z *= inv; a.w *= inv;
    ((float4*)outm)[hw * 16 + c] = a;
}

// ---------------- HMMA bf16 3-pass GEMM, 256 threads, ldmatrix ---------------
// Staging uses float8 steps: 2x LDG.128 -> one 16B hi STS.128 + one 16B lo STS.128.
#define ASTRIDE_W 68            // words per smem row (136 bf16: 128 + 8 pad)
#define OFF_BIAS 0
#define OFF_AHI  256
#define OFF_ALO  (OFF_AHI + 128 * ASTRIDE_W * 4)
#define OFF_BHI  (OFF_ALO + 128 * ASTRIDE_W * 4)
#define OFF_BLO  (OFF_BHI + 64 * ASTRIDE_W * 4)
#define GEMM_SMEM (OFF_BLO + 64 * ASTRIDE_W * 4)    // 104704 B

__device__ __forceinline__ void hilo_pack(float4 v, uint32_t& h01, uint32_t& h23,
                                          uint32_t& l01, uint32_t& l23) {
    uint32_t u0 = __float_as_uint(v.x), u1 = __float_as_uint(v.y);
    uint32_t u2 = __float_as_uint(v.z), u3 = __float_as_uint(v.w);
    float h0 = __uint_as_float(u0 & 0xFFFF0000u);
    float h1 = __uint_as_float(u1 & 0xFFFF0000u);
    float h2 = __uint_as_float(u2 & 0xFFFF0000u);
    float h3 = __uint_as_float(u3 & 0xFFFF0000u);
    h01 = (u0 >> 16) | (u1 & 0xFFFF0000u);
    h23 = (u2 >> 16) | (u3 & 0xFFFF0000u);
    float l0 = v.x - h0, l1 = v.y - h1, l2 = v.z - h2, l3 = v.w - h3;
    asm("cvt.rn.bf16x2.f32 %0, %1, %2;" : "=r"(l01) : "f"(l1), "f"(l0));
    asm("cvt.rn.bf16x2.f32 %0, %1, %2;" : "=r"(l23) : "f"(l3), "f"(l2));
}

__device__ __forceinline__ void mma16816(float* d, uint32_t a0, uint32_t a1,
                                         uint32_t a2, uint32_t a3,
                                         uint32_t b0, uint32_t b1) {
    asm volatile(
        "mma.sync.aligned.m16n8k16.row.col.f32.bf16.bf16.f32 "
        "{%0,%1,%2,%3}, {%4,%5,%6,%7}, {%8,%9}, {%0,%1,%2,%3};"
        : "+f"(d[0]), "+f"(d[1]), "+f"(d[2]), "+f"(d[3])
        : "r"(a0), "r"(a1), "r"(a2), "r"(a3), "r"(b0), "r"(b1));
}

#define LDSM4(r0, r1, r2, r3, addr) \
    asm volatile("ldmatrix.sync.aligned.m8n8.x4.shared.b16 {%0,%1,%2,%3}, [%4];" \
                 : "=r"(r0), "=r"(r1), "=r"(r2), "=r"(r3) : "r"(addr))

__global__ __launch_bounds__(256) void k_gemm_mma(
    const float* __restrict__ meanp, const float* __restrict__ xp,
    const float* __restrict__ Wl, const float* __restrict__ Wr,
    const float* __restrict__ bias, float* __restrict__ outp, int do_relu)
{
    extern __shared__ char smc[];
    int tid = threadIdx.x;
    int wid = tid >> 5, lane = tid & 31;
    int node0 = blockIdx.x * 128;

    if (tid < 64) *(float*)(smc + OFF_BIAS + tid * 4) = bias[tid];

    uint32_t* AhW = (uint32_t*)(smc + OFF_AHI);
    uint32_t* AlW = (uint32_t*)(smc + OFF_ALO);
    uint32_t* BhW = (uint32_t*)(smc + OFF_BHI);
    uint32_t* BlW = (uint32_t*)(smc + OFF_BLO);

    // ---- stage A: 128 rows x 128 k, float8 per thread-iter ----
    {
        int k8 = tid & 15;          // 16 chunks of 8 floats per row
        int ms = tid >> 4;          // 0..15
        int kk = k8 * 8;            // chunk never straddles mean/x (kk in {0..120})
        const float* basep = (kk < 64) ? (meanp + kk) : (xp + kk - 64);
#pragma unroll
        for (int m = ms; m < 128; m += 16) {
            int node = node0 + m;
            float4 v0 = make_float4(0.f, 0.f, 0.f, 0.f);
            float4 v1 = v0;
            if (node < NN) {
                v0 = *(const float4*)(basep + node * D);
                v1 = *(const float4*)(basep + node * D + 4);
            }
            uint32_t ha0, ha1, la0, la1, hb0, hb1, lb0, lb1;
            hilo_pack(v0, ha0, ha1, la0, la1);
            hilo_pack(v1, hb0, hb1, lb0, lb1);
            int w = m * ASTRIDE_W + (kk >> 1);          // word offset, 16B aligned
            *(uint4*)(AhW + w) = make_uint4(ha0, ha1, hb0, hb1);
            *(uint4*)(AlW + w) = make_uint4(la0, la1, lb0, lb1);
        }
    }
    // ---- stage B: 64 rows x 128 k, float8 per thread-iter ----
    {
        int k8 = tid & 15;
        int js = tid >> 4;
        int kk = k8 * 8;
        const float* basep = (kk < 64) ? (Wl + kk) : (Wr + kk - 64);
#pragma unroll
        for (int j = js; j < 64; j += 16) {
            float4 v0 = *(const float4*)(basep + j * 64);
            float4 v1 = *(const float4*)(basep + j * 64 + 4);
            uint32_t ha0, ha1, la0, la1, hb0, hb1, lb0, lb1;
            hilo_pack(v0, ha0, ha1, la0, la1);
            hilo_pack(v1, hb0, hb1, lb0, lb1);
            int w = j * ASTRIDE_W + (kk >> 1);
            *(uint4*)(BhW + w) = make_uint4(ha0, ha1, hb0, hb1);
            *(uint4*)(BlW + w) = make_uint4(la0, la1, lb0, lb1);
        }
    }
    __syncthreads();

    // ---- main loop via ldmatrix: warp w -> rows [w*16, w*16+16) ----
    uint32_t sAh = (uint32_t)__cvta_generic_to_shared(smc + OFF_AHI);
    uint32_t sAl = (uint32_t)__cvta_generic_to_shared(smc + OFF_ALO);
    uint32_t sBh = (uint32_t)__cvta_generic_to_shared(smc + OFF_BHI);
    uint32_t sBl = (uint32_t)__cvta_generic_to_shared(smc + OFF_BLO);

    uint32_t aoff = (uint32_t)(((wid * 16 + (lane & 15)) * ASTRIDE_W + (lane >> 4) * 4) * 4);
    uint32_t boff = (uint32_t)(((((lane >> 3) >> 1) * 8 + (lane & 7)) * ASTRIDE_W
                               + ((lane >> 3) & 1) * 4) * 4);

    float acc[8][4];
#pragma unroll
    for (int nt = 0; nt < 8; nt++)
#pragma unroll
        for (int r = 0; r < 4; r++) acc[nt][r] = 0.f;

    int r4 = lane >> 2;
    int c4 = lane & 3;

#pragma unroll
    for (int ks = 0; ks < 8; ks++) {
        uint32_t kb = (uint32_t)(ks * 32);      // 8 words per ks

        uint32_t bh[8][2], bl[8][2];
#pragma unroll
        for (int ntp = 0; ntp < 4; ntp++) {
            uint32_t ob = boff + (uint32_t)(ntp * 16 * ASTRIDE_W * 4) + kb;
            LDSM4(bh[2 * ntp][0], bh[2 * ntp][1], bh[2 * ntp + 1][0], bh[2 * ntp + 1][1],
                  sBh + ob);
            LDSM4(bl[2 * ntp][0], bl[2 * ntp][1], bl[2 * ntp + 1][0], bl[2 * ntp + 1][1],
                  sBl + ob);
        }
        uint32_t oa = aoff + kb;
        uint32_t ah0, ah1, ah2, ah3, al0, al1, al2, al3;
        LDSM4(ah0, ah1, ah2, ah3, sAh + oa);
        LDSM4(al0, al1, al2, al3, sAl + oa);
#pragma unroll
        for (int nt = 0; nt < 8; nt++) {
            mma16816(acc[nt], ah0, ah1, ah2, ah3, bh[nt][0], bh[nt][1]);
            mma16816(acc[nt], ah0, ah1, ah2, ah3, bl[nt][0], bl[nt][1]);
            mma16816(acc[nt], al0, al1, al2, al3, bh[nt][0], bh[nt][1]);
        }
    }

    // ---- epilogue ----
    const float* bsm = (const float*)(smc + OFF_BIAS);
    int row0 = node0 + wid * 16 + r4;
#pragma unroll
    for (int nt = 0; nt < 8; nt++) {
        int col = nt * 8 + 2 * c4;
        float bx = bsm[col], by = bsm[col + 1];
        float f0 = acc[nt][0] + bx, f1 = acc[nt][1] + by;
        float f2 = acc[nt][2] + bx, f3 = acc[nt][3] + by;
        if (do_relu) {
            f0 = fmaxf(f0, 0.f); f1 = fmaxf(f1, 0.f);
            f2 = fmaxf(f2, 0.f); f3 = fmaxf(f3, 0.f);
        }
        if (row0 < NN)     *(float2*)(outp + row0 * D + col)       = make_float2(f0, f1);
        if (row0 + 8 < NN) *(float2*)(outp + (row0 + 8) * D + col) = make_float2(f2, f3);
    }
}

// ---------------- launch -----------------------------------------------------
extern "C" void kernel_launch(void* const* d_in, const int* in_sizes, int n_in,
                              void* d_out, int out_size)
{
    const float* x   = (const float*)d_in[0];
    const void*  ei  = d_in[1];
    const float* W1l = (const float*)d_in[2];
    const float* b1l = (const float*)d_in[3];
    const float* W1r = (const float*)d_in[4];
    const float* W2l = (const float*)d_in[5];
    const float* b2l = (const float*)d_in[6];
    const float* W2r = (const float*)d_in[7];
    float* out = (float*)d_out;

    cudaFuncSetAttribute(k_gemm_mma, cudaFuncAttributeMaxDynamicSharedMemorySize, GEMM_SMEM);

    float* d_mean; cudaGetSymbolAddress((void**)&d_mean, g_meanbuf);
    float* d_h;    cudaGetSymbolAddress((void**)&d_h, g_h);

    int hist_grid = (NE / HIST_ILP + 255) / 256;   // 1954
    int fill_grid = (NE / EDGE_ILP + 255) / 256;   // 977

    k_init<<<(NN + 255) / 256, 256>>>((const long long*)ei);
    k_hist<<<hist_grid, 256>>>(ei);
    k_scan<<<SCAN_NB, SCAN_B>>>();
    k_fill<<<fill_grid, 256>>>(ei);

    int agg_grid = (NN * 16 + 255) / 256;   // half-warp per node
    int grid     = (NN + 127) / 128;        // 782

    k_agg     <<<agg_grid, 256>>>(x, d_mean);
    k_gemm_mma<<<grid, 256, GEMM_SMEM>>>(d_mean, x, W1l, W1r, b1l, d_h, 1);
    k_agg     <<<agg_grid, 256>>>(d_h, d_mean);
    k_gemm_mma<<<grid, 256, GEMM_SMEM>>>(d_mean, d_h, W2l, W2r, b2l, out, 0);
}

// round 13
// speedup vs baseline: 1.0363x; 1.0363x over previous
#include <cuda_runtime.h>
#include <cuda_bf16.h>
#include <math.h>
#include <stdint.h>

#define NN 100000
#define NE 1000000
#define D  64

// ---------------- scratch ----------------------------------------------------
__device__ int      g_deg[NN];        // invariant: all-zero at kernel_launch entry/exit
__device__ int      g_off[NN + 1];
__device__ int      g_rank[NE];
__device__ int      g_adj[NE];
__device__ float    g_h[NN * D];
__device__ float    g_meanbuf[NN * D];
__device__ unsigned g_scanpub[128];   // invariant: all-zero at entry/exit (fill clears)

#define SCAN_B 1024
#define SCAN_NB ((NN + SCAN_B - 1) / SCAN_B)   // 98

// ---------------- edge dtype handling ---------------------------------------
__device__ __forceinline__ int edge_at(const void* ei, int idx, int is64) {
    if (is64) return (int)((const long long*)ei)[idx];
    return ((const int*)ei)[idx];
}

// Per-warp dtype probe: sample first 128 int64 words. If the buffer is int32
// (x64-disabled JAX), high words are the next edge values — nonzero with
// prob 1-1e-5 each, so all-128-zero is impossible in practice. Deterministic:
// every warp computes the same answer from the same data.
__device__ __forceinline__ int probe_is64(const void* ei) {
    const long long* e64 = (const long long*)ei;
    int lane = threadIdx.x & 31;
    int bad = 0;
#pragma unroll
    for (int u = 0; u < 4; u++) {
        long long v = e64[lane + 32 * u];
        if (v < 0 || v >= NN) bad = 1;
    }
    return __ballot_sync(0xFFFFFFFFu, bad) == 0u;
}

// ---------------- CSR build --------------------------------------------------
// hist assigns each edge its within-bucket rank via the atomicAdd return value;
// fill then needs NO atomics at all.
#define HIST_ILP 4
__global__ void k_hist(const void* __restrict__ ei) {
    int gid = blockIdx.x * blockDim.x + threadIdx.x;
    int stride = gridDim.x * blockDim.x;
    int is64 = probe_is64(ei);
    int dst[HIST_ILP];
#pragma unroll
    for (int u = 0; u < HIST_ILP; u++) {
        int e = gid + u * stride;
        dst[u] = (e < NE) ? edge_at(ei, NE + e, is64) : -1;
    }
    int rk[HIST_ILP];
#pragma unroll
    for (int u = 0; u < HIST_ILP; u++)
        rk[u] = ((unsigned)dst[u] < NN) ? atomicAdd(&g_deg[dst[u]], 1) : -1;
#pragma unroll
    for (int u = 0; u < HIST_ILP; u++) {
        int e = gid + u * stride;
        if (rk[u] >= 0) g_rank[e] = rk[u];
    }
}

// single-pass exclusive scan with decoupled lookback.
// Also: re-zeroes g_deg after reading (maintains the zero invariant for the
// next call) and writes the g_off[NN] = total sentinel.
__global__ __launch_bounds__(SCAN_B) void k_scan(void) {
    __shared__ int wsum[32];
    __shared__ int s_base;
    int tid = threadIdx.x, lane = tid & 31, w = tid >> 5;
    int i = blockIdx.x * SCAN_B + tid;
    int v = (i < NN) ? g_deg[i] : 0;
    int p = v;
#pragma unroll
    for (int st = 1; st < 32; st <<= 1) {
        int t = __shfl_up_sync(0xFFFFFFFFu, p, st);
        if (lane >= st) p += t;
    }
    if (lane == 31) wsum[w] = p;
    if (tid == 0) s_base = 0;
    __syncthreads();
    if (w == 0) {
        int s = wsum[lane];
#pragma unroll
        for (int st = 1; st < 32; st <<= 1) {
            int t = __shfl_up_sync(0xFFFFFFFFu, s, st);
            if (lane >= st) s += t;
        }
        wsum[lane] = s;
    }
    __syncthreads();
    int wbase = (w > 0) ? wsum[w - 1] : 0;
    int incl = wbase + p;
    if (tid == SCAN_B - 1)
        ((volatile unsigned*)g_scanpub)[blockIdx.x] = 0x80000000u | (unsigned)incl;
    if (tid < blockIdx.x) {
        unsigned u;
        do { u = ((volatile unsigned*)g_scanpub)[tid]; } while (!(u & 0x80000000u));
        atomicAdd(&s_base, (int)(u & 0x7FFFFFFFu));
    }
    __syncthreads();
    if (i < NN) {
        g_off[i] = s_base + incl - v;
        g_deg[i] = 0;                       // restore invariant
        if (i == NN - 1) g_off[NN] = s_base + incl;   // sentinel (= NE)
    }
}

// atomic-free fill: slot = off[dst] + rank[e]. Also clears scanpub flags.
#define FILL_ILP 2
__global__ void k_fill(const void* __restrict__ ei) {
    int gid = blockIdx.x * blockDim.x + threadIdx.x;
    int stride = gridDim.x * blockDim.x;
    if (gid < SCAN_NB) g_scanpub[gid] = 0u;   // restore invariant for next call
    int is64 = probe_is64(ei);
    int src[FILL_ILP], dst[FILL_ILP], rk[FILL_ILP];
#pragma unroll
    for (int u = 0; u < FILL_ILP; u++) {
        int e = gid + u * stride;
        if (e < NE) {
            src[u] = edge_at(ei, e, is64);
            dst[u] = edge_at(ei, NE + e, is64);
            rk[u]  = g_rank[e];
        } else { src[u] = -1; dst[u] = -1; rk[u] = 0; }
    }
    int base[FILL_ILP];
#pragma unroll
    for (int u = 0; u < FILL_ILP; u++)
        base[u] = ((unsigned)dst[u] < NN) ? __ldg(&g_off[dst[u]]) : -1;
#pragma unroll
    for (int u = 0; u < FILL_ILP; u++)
        if (base[u] >= 0 && (unsigned)src[u] < NN)
            g_adj[base[u] + rk[u]] = src[u];
}

// ---------------- mean aggregation: half-warp per node, float4 --------------
__global__ void k_agg(const float* __restrict__ feat, float* __restrict__ outm) {
    int hw = (blockIdx.x * blockDim.x + threadIdx.x) >> 4;  // node id
    int c  = threadIdx.x & 15;                              // float4 lane
    if (hw >= NN) return;
    int o = g_off[hw];
    int d = g_off[hw + 1] - o;
    const float4* f4 = (const float4*)feat;
    float4 a = make_float4(0.f, 0.f, 0.f, 0.f);
    int t = 0;
    for (; t + 4 <= d; t += 4) {
        int nb0 = g_adj[o + t];
        int nb1 = g_adj[o + t + 1];
        int nb2 = g_adj[o + t + 2];
        int nb3 = g_adj[o + t + 3];
        float4 v0 = f4[nb0 * 16 + c];
        float4 v1 = f4[nb1 * 16 + c];
        float4 v2 = f4[nb2 * 16 + c];
        float4 v3 = f4[nb3 * 16 + c];
        a.x += v0.x + v1.x + v2.x + v3.x;
        a.y += v0.y + v1.y + v2.y + v3.y;
        a.z += v0.z + v1.z + v2.z + v3.z;
        a.w += v0.w + v1.w + v2.w + v3.w;
    }
    for (; t < d; t++) {
        int nb = g_adj[o + t];
        float4 v = f4[nb * 16 + c];
        a.x += v.x; a.y += v.y; a.z += v.z; a.w += v.w;
    }
    float inv = 1.0f / (float)max(d, 1);
    a.x *= inv; a.y *= inv; a.z *= inv; a.w *= inv;
    ((float4*)outm)[hw * 16 + c] = a;
}

// ---------------- HMMA bf16 3-pass GEMM, 256 threads, ldmatrix ---------------
#define ASTRIDE_W 68            // words per smem row (136 bf16: 128 + 8 pad)
#define OFF_BIAS 0
#define OFF_AHI  256
#define OFF_ALO  (OFF_AHI + 128 * ASTRIDE_W * 4)
#define OFF_BHI  (OFF_ALO + 128 * ASTRIDE_W * 4)
#define OFF_BLO  (OFF_BHI + 64 * ASTRIDE_W * 4)
#define GEMM_SMEM (OFF_BLO + 64 * ASTRIDE_W * 4)    // 104704 B

__device__ __forceinline__ void hilo_pack(float4 v, uint32_t& h01, uint32_t& h23,
                                          uint32_t& l01, uint32_t& l23) {
    uint32_t u0 = __float_as_uint(v.x), u1 = __float_as_uint(v.y);
    uint32_t u2 = __float_as_uint(v.z), u3 = __float_as_uint(v.w);
    float h0 = __uint_as_float(u0 & 0xFFFF0000u);
    float h1 = __uint_as_float(u1 & 0xFFFF0000u);
    float h2 = __uint_as_float(u2 & 0xFFFF0000u);
    float h3 = __uint_as_float(u3 & 0xFFFF0000u);
    h01 = (u0 >> 16) | (u1 & 0xFFFF0000u);
    h23 = (u2 >> 16) | (u3 & 0xFFFF0000u);
    float l0 = v.x - h0, l1 = v.y - h1, l2 = v.z - h2, l3 = v.w - h3;
    asm("cvt.rn.bf16x2.f32 %0, %1, %2;" : "=r"(l01) : "f"(l1), "f"(l0));
    asm("cvt.rn.bf16x2.f32 %0, %1, %2;" : "=r"(l23) : "f"(l3), "f"(l2));
}

__device__ __forceinline__ void mma16816(float* d, uint32_t a0, uint32_t a1,
                                         uint32_t a2, uint32_t a3,
                                         uint32_t b0, uint32_t b1) {
    asm volatile(
        "mma.sync.aligned.m16n8k16.row.col.f32.bf16.bf16.f32 "
        "{%0,%1,%2,%3}, {%4,%5,%6,%7}, {%8,%9}, {%0,%1,%2,%3};"
        : "+f"(d[0]), "+f"(d[1]), "+f"(d[2]), "+f"(d[3])
        : "r"(a0), "r"(a1), "r"(a2), "r"(a3), "r"(b0), "r"(b1));
}

#define LDSM4(r0, r1, r2, r3, addr) \
    asm volatile("ldmatrix.sync.aligned.m8n8.x4.shared.b16 {%0,%1,%2,%3}, [%4];" \
                 : "=r"(r0), "=r"(r1), "=r"(r2), "=r"(r3) : "r"(addr))

__global__ __launch_bounds__(256) void k_gemm_mma(
    const float* __restrict__ meanp, const float* __restrict__ xp,
    const float* __restrict__ Wl, const float* __restrict__ Wr,
    const float* __restrict__ bias, float* __restrict__ outp, int do_relu)
{
    extern __shared__ char smc[];
    int tid = threadIdx.x;
    int wid = tid >> 5, lane = tid & 31;
    int node0 = blockIdx.x * 128;

    if (tid < 64) *(float*)(smc + OFF_BIAS + tid * 4) = bias[tid];

    uint2* Ah = (uint2*)(smc + OFF_AHI);
    uint2* Al = (uint2*)(smc + OFF_ALO);
    uint2* Bh = (uint2*)(smc + OFF_BHI);
    uint2* Bl = (uint2*)(smc + OFF_BLO);

    // ---- stage A: 128 rows x 128 k ----
    {
        int k4 = tid & 31;
        int ms = tid >> 5;          // 0..7
        int kk = k4 * 4;
        const float* basep = (kk < 64) ? (meanp + kk) : (xp + kk - 64);
#pragma unroll 4
        for (int m = ms; m < 128; m += 8) {
            int node = node0 + m;
            float4 v = make_float4(0.f, 0.f, 0.f, 0.f);
            if (node < NN) v = *(const float4*)(basep + node * D);
            uint32_t h01, h23, l01, l23;
            hilo_pack(v, h01, h23, l01, l23);
            int w2 = (m * ASTRIDE_W + (kk >> 1)) >> 1;
            Ah[w2] = make_uint2(h01, h23);
            Al[w2] = make_uint2(l01, l23);
        }
    }
    // ---- stage B: 64 rows x 128 k ----
    {
        int k4 = tid & 31;
        int js = tid >> 5;
        int kk = k4 * 4;
        const float* basep = (kk < 64) ? (Wl + kk) : (Wr + kk - 64);
#pragma unroll 4
        for (int j = js; j < 64; j += 8) {
            float4 v = *(const float4*)(basep + j * 64);
            uint32_t h01, h23, l01, l23;
            hilo_pack(v, h01, h23, l01, l23);
            int w2 = (j * ASTRIDE_W + (kk >> 1)) >> 1;
            Bh[w2] = make_uint2(h01, h23);
            Bl[w2] = make_uint2(l01, l23);
        }
    }
    __syncthreads();

    // ---- main loop via ldmatrix: warp w -> rows [w*16, w*16+16) ----
    uint32_t sAh = (uint32_t)__cvta_generic_to_shared(smc + OFF_AHI);
    uint32_t sAl = (uint32_t)__cvta_generic_to_shared(smc + OFF_ALO);
    uint32_t sBh = (uint32_t)__cvta_generic_to_shared(smc + OFF_BHI);
    uint32_t sBl = (uint32_t)__cvta_generic_to_shared(smc + OFF_BLO);

    uint32_t aoff = (uint32_t)(((wid * 16 + (lane & 15)) * ASTRIDE_W + (lane >> 4) * 4) * 4);
    uint32_t boff = (uint32_t)(((((lane >> 3) >> 1) * 8 + (lane & 7)) * ASTRIDE_W
                               + ((lane >> 3) & 1) * 4) * 4);

    float acc[8][4];
#pragma unroll
    for (int nt = 0; nt < 8; nt++)
#pragma unroll
        for (int r = 0; r < 4; r++) acc[nt][r] = 0.f;

    int r4 = lane >> 2;
    int c4 = lane & 3;

#pragma unroll
    for (int ks = 0; ks < 8; ks++) {
        uint32_t kb = (uint32_t)(ks * 32);      // 8 words per ks

        uint32_t bh[8][2], bl[8][2];
#pragma unroll
        for (int ntp = 0; ntp < 4; ntp++) {
            uint32_t ob = boff + (uint32_t)(ntp * 16 * ASTRIDE_W * 4) + kb;
            LDSM4(bh[2 * ntp][0], bh[2 * ntp][1], bh[2 * ntp + 1][0], bh[2 * ntp + 1][1],
                  sBh + ob);
            LDSM4(bl[2 * ntp][0], bl[2 * ntp][1], bl[2 * ntp + 1][0], bl[2 * ntp + 1][1],
                  sBl + ob);
        }
        uint32_t oa = aoff + kb;
        uint32_t ah0, ah1, ah2, ah3, al0, al1, al2, al3;
        LDSM4(ah0, ah1, ah2, ah3, sAh + oa);
        LDSM4(al0, al1, al2, al3, sAl + oa);
#pragma unroll
        for (int nt = 0; nt < 8; nt++) {
            mma16816(acc[nt], ah0, ah1, ah2, ah3, bh[nt][0], bh[nt][1]);
            mma16816(acc[nt], ah0, ah1, ah2, ah3, bl[nt][0], bl[nt][1]);
            mma16816(acc[nt], al0, al1, al2, al3, bh[nt][0], bh[nt][1]);
        }
    }

    // ---- epilogue ----
    const float* bsm = (const float*)(smc + OFF_BIAS);
    int row0 = node0 + wid * 16 + r4;
#pragma unroll
    for (int nt = 0; nt < 8; nt++) {
        int col = nt * 8 + 2 * c4;
        float bx = bsm[col], by = bsm[col + 1];
        float f0 = acc[nt][0] + bx, f1 = acc[nt][1] + by;
        float f2 = acc[nt][2] + bx, f3 = acc[nt][3] + by;
        if (do_relu) {
            f0 = fmaxf(f0, 0.f); f1 = fmaxf(f1, 0.f);
            f2 = fmaxf(f2, 0.f); f3 = fmaxf(f3, 0.f);
        }
        if (row0 < NN)     *(float2*)(outp + row0 * D + col)       = make_float2(f0, f1);
        if (row0 + 8 < NN) *(float2*)(outp + (row0 + 8) * D + col) = make_float2(f2, f3);
    }
}

// ---------------- launch -----------------------------------------------------
extern "C" void kernel_launch(void* const* d_in, const int* in_sizes, int n_in,
                              void* d_out, int out_size)
{
    const float* x   = (const float*)d_in[0];
    const void*  ei  = d_in[1];
    const float* W1l = (const float*)d_in[2];
    const float* b1l = (const float*)d_in[3];
    const float* W1r = (const float*)d_in[4];
    const float* W2l = (const float*)d_in[5];
    const float* b2l = (const float*)d_in[6];
    const float* W2r = (const float*)d_in[7];
    float* out = (float*)d_out;

    cudaFuncSetAttribute(k_gemm_mma, cudaFuncAttributeMaxDynamicSharedMemorySize, GEMM_SMEM);

    float* d_mean; cudaGetSymbolAddress((void**)&d_mean, g_meanbuf);
    float* d_h;    cudaGetSymbolAddress((void**)&d_h, g_h);

    int hist_grid = (NE / HIST_ILP + 255) / 256;   // 977
    int fill_grid = (NE / FILL_ILP + 255) / 256;   // 1954

    k_hist<<<hist_grid, 256>>>(ei);
    k_scan<<<SCAN_NB, SCAN_B>>>();
    k_fill<<<fill_grid, 256>>>(ei);

    int agg_grid = (NN * 16 + 255) / 256;   // half-warp per node
    int grid     = (NN + 127) / 128;        // 782

    k_agg     <<<agg_grid, 256>>>(x, d_mean);
    k_gemm_mma<<<grid, 256, GEMM_SMEM>>>(d_mean, x, W1l, W1r, b1l, d_h, 1);
    k_agg     <<<agg_grid, 256>>>(d_h, d_mean);
    k_gemm_mma<<<grid, 256, GEMM_SMEM>>>(d_mean, d_h, W2l, W2r, b2l, out, 0);
}

// round 14
// speedup vs baseline: 1.0491x; 1.0123x over previous
#include <cuda_runtime.h>
#include <cuda_bf16.h>
#include <math.h>
#include <stdint.h>

#define NN 100000
#define NE 1000000
#define D  64

// ---------------- scratch ----------------------------------------------------
__device__ int      g_deg[NN];        // invariant: all-zero at kernel_launch entry/exit
__device__ int      g_off[NN + 1];
__device__ int      g_rank[NE];
__device__ int      g_adj[NE];
__device__ float    g_h[NN * D];
__device__ float    g_meanbuf[NN * D];
__device__ unsigned g_scanpub[128];   // invariant: all-zero at entry/exit (fill clears)

#define SCAN_B 1024
#define SCAN_NB ((NN + SCAN_B - 1) / SCAN_B)   // 98

// ---------------- edge dtype handling ---------------------------------------
__device__ __forceinline__ int edge_at(const void* ei, int idx, int is64) {
    if (is64) return (int)((const long long*)ei)[idx];
    return ((const int*)ei)[idx];
}

// Per-warp dtype probe: sample first 128 int64 words. If the buffer is int32
// (x64-disabled JAX), high words are the next edge values — nonzero with
// prob 1-1e-5 each, so all-128-zero is impossible in practice.
__device__ __forceinline__ int probe_is64(const void* ei) {
    const long long* e64 = (const long long*)ei;
    int lane = threadIdx.x & 31;
    int bad = 0;
#pragma unroll
    for (int u = 0; u < 4; u++) {
        long long v = e64[lane + 32 * u];
        if (v < 0 || v >= NN) bad = 1;
    }
    return __ballot_sync(0xFFFFFFFFu, bad) == 0u;
}

// ---------------- CSR build --------------------------------------------------
#define HIST_ILP 4
__global__ void k_hist(const void* __restrict__ ei) {
    int gid = blockIdx.x * blockDim.x + threadIdx.x;
    int stride = gridDim.x * blockDim.x;
    int is64 = probe_is64(ei);
    int dst[HIST_ILP];
#pragma unroll
    for (int u = 0; u < HIST_ILP; u++) {
        int e = gid + u * stride;
        dst[u] = (e < NE) ? edge_at(ei, NE + e, is64) : -1;
    }
    int rk[HIST_ILP];
#pragma unroll
    for (int u = 0; u < HIST_ILP; u++)
        rk[u] = ((unsigned)dst[u] < NN) ? atomicAdd(&g_deg[dst[u]], 1) : -1;
#pragma unroll
    for (int u = 0; u < HIST_ILP; u++) {
        int e = gid + u * stride;
        if (rk[u] >= 0) g_rank[e] = rk[u];
    }
}

// single-pass exclusive scan with decoupled lookback; restores g_deg=0 and
// writes the g_off[NN] sentinel.
__global__ __launch_bounds__(SCAN_B) void k_scan(void) {
    __shared__ int wsum[32];
    __shared__ int s_base;
    int tid = threadIdx.x, lane = tid & 31, w = tid >> 5;
    int i = blockIdx.x * SCAN_B + tid;
    int v = (i < NN) ? g_deg[i] : 0;
    int p = v;
#pragma unroll
    for (int st = 1; st < 32; st <<= 1) {
        int t = __shfl_up_sync(0xFFFFFFFFu, p, st);
        if (lane >= st) p += t;
    }
    if (lane == 31) wsum[w] = p;
    if (tid == 0) s_base = 0;
    __syncthreads();
    if (w == 0) {
        int s = wsum[lane];
#pragma unroll
        for (int st = 1; st < 32; st <<= 1) {
            int t = __shfl_up_sync(0xFFFFFFFFu, s, st);
            if (lane >= st) s += t;
        }
        wsum[lane] = s;
    }
    __syncthreads();
    int wbase = (w > 0) ? wsum[w - 1] : 0;
    int incl = wbase + p;
    if (tid == SCAN_B - 1)
        ((volatile unsigned*)g_scanpub)[blockIdx.x] = 0x80000000u | (unsigned)incl;
    if (tid < blockIdx.x) {
        unsigned u;
        do { u = ((volatile unsigned*)g_scanpub)[tid]; } while (!(u & 0x80000000u));
        atomicAdd(&s_base, (int)(u & 0x7FFFFFFFu));
    }
    __syncthreads();
    if (i < NN) {
        g_off[i] = s_base + incl - v;
        g_deg[i] = 0;                       // restore invariant
        if (i == NN - 1) g_off[NN] = s_base + incl;   // sentinel (= NE)
    }
}

// atomic-free fill: slot = off[dst] + rank[e]. Also clears scanpub flags.
#define FILL_ILP 2
__global__ void k_fill(const void* __restrict__ ei) {
    int gid = blockIdx.x * blockDim.x + threadIdx.x;
    int stride = gridDim.x * blockDim.x;
    if (gid < SCAN_NB) g_scanpub[gid] = 0u;   // restore invariant for next call
    int is64 = probe_is64(ei);
    int src[FILL_ILP], dst[FILL_ILP], rk[FILL_ILP];
#pragma unroll
    for (int u = 0; u < FILL_ILP; u++) {
        int e = gid + u * stride;
        if (e < NE) {
            src[u] = edge_at(ei, e, is64);
            dst[u] = edge_at(ei, NE + e, is64);
            rk[u]  = g_rank[e];
        } else { src[u] = -1; dst[u] = -1; rk[u] = 0; }
    }
    int base[FILL_ILP];
#pragma unroll
    for (int u = 0; u < FILL_ILP; u++)
        base[u] = ((unsigned)dst[u] < NN) ? __ldg(&g_off[dst[u]]) : -1;
#pragma unroll
    for (int u = 0; u < FILL_ILP; u++)
        if (base[u] >= 0 && (unsigned)src[u] < NN)
            g_adj[base[u] + rk[u]] = src[u];
}

// ---------------- mean aggregation: half-warp per node, shuffle-bcast -------
// Each lane loads ONE coalesced index per 16-neighbor chunk; shfl(width=16)
// broadcasts it to the half-warp; 16 independent predicated float4 gathers.
__global__ void k_agg(const float* __restrict__ feat, float* __restrict__ outm) {
    int hw = (blockIdx.x * blockDim.x + threadIdx.x) >> 4;  // node id (grid exact)
    int c  = threadIdx.x & 15;                              // float4 lane
    unsigned mask = 0xFFFFu << (threadIdx.x & 16);          // own half-warp lanes
    int o = g_off[hw];
    int d = g_off[hw + 1] - o;
    const float4* f4 = (const float4*)feat;
    float4 a = make_float4(0.f, 0.f, 0.f, 0.f);
    for (int t = 0; t < d; t += 16) {
        int idx = (t + c < d) ? g_adj[o + t + c] : 0;
#pragma unroll
        for (int u = 0; u < 16; u++) {
            int nb = __shfl_sync(mask, idx, u, 16);
            if (t + u < d) {
                float4 v = f4[nb * 16 + c];
                a.x += v.x; a.y += v.y; a.z += v.z; a.w += v.w;
            }
        }
    }
    float inv = 1.0f / (float)max(d, 1);
    a.x *= inv; a.y *= inv; a.z *= inv; a.w *= inv;
    ((float4*)outm)[hw * 16 + c] = a;
}

// ---------------- HMMA bf16 3-pass GEMM, 256 threads, ldmatrix ---------------
#define ASTRIDE_W 68            // words per smem row (136 bf16: 128 + 8 pad)
#define OFF_BIAS 0
#define OFF_AHI  256
#define OFF_ALO  (OFF_AHI + 128 * ASTRIDE_W * 4)
#define OFF_BHI  (OFF_ALO + 128 * ASTRIDE_W * 4)
#define OFF_BLO  (OFF_BHI + 64 * ASTRIDE_W * 4)
#define GEMM_SMEM (OFF_BLO + 64 * ASTRIDE_W * 4)    // 104704 B

__device__ __forceinline__ void hilo_pack(float4 v, uint32_t& h01, uint32_t& h23,
                                          uint32_t& l01, uint32_t& l23) {
    uint32_t u0 = __float_as_uint(v.x), u1 = __float_as_uint(v.y);
    uint32_t u2 = __float_as_uint(v.z), u3 = __float_as_uint(v.w);
    float h0 = __uint_as_float(u0 & 0xFFFF0000u);
    float h1 = __uint_as_float(u1 & 0xFFFF0000u);
    float h2 = __uint_as_float(u2 & 0xFFFF0000u);
    float h3 = __uint_as_float(u3 & 0xFFFF0000u);
    h01 = (u0 >> 16) | (u1 & 0xFFFF0000u);
    h23 = (u2 >> 16) | (u3 & 0xFFFF0000u);
    float l0 = v.x - h0, l1 = v.y - h1, l2 = v.z - h2, l3 = v.w - h3;
    asm("cvt.rn.bf16x2.f32 %0, %1, %2;" : "=r"(l01) : "f"(l1), "f"(l0));
    asm("cvt.rn.bf16x2.f32 %0, %1, %2;" : "=r"(l23) : "f"(l3), "f"(l2));
}

__device__ __forceinline__ void mma16816(float* d, uint32_t a0, uint32_t a1,
                                         uint32_t a2, uint32_t a3,
                                         uint32_t b0, uint32_t b1) {
    asm volatile(
        "mma.sync.aligned.m16n8k16.row.col.f32.bf16.bf16.f32 "
        "{%0,%1,%2,%3}, {%4,%5,%6,%7}, {%8,%9}, {%0,%1,%2,%3};"
        : "+f"(d[0]), "+f"(d[1]), "+f"(d[2]), "+f"(d[3])
        : "r"(a0), "r"(a1), "r"(a2), "r"(a3), "r"(b0), "r"(b1));
}

#define LDSM4(r0, r1, r2, r3, addr) \
    asm volatile("ldmatrix.sync.aligned.m8n8.x4.shared.b16 {%0,%1,%2,%3}, [%4];" \
                 : "=r"(r0), "=r"(r1), "=r"(r2), "=r"(r3) : "r"(addr))

__global__ __launch_bounds__(256) void k_gemm_mma(
    const float* __restrict__ meanp, const float* __restrict__ xp,
    const float* __restrict__ Wl, const float* __restrict__ Wr,
    const float* __restrict__ bias, float* __restrict__ outp, int do_relu)
{
    extern __shared__ char smc[];
    int tid = threadIdx.x;
    int wid = tid >> 5, lane = tid & 31;
    int node0 = blockIdx.x * 128;

    if (tid < 64) *(float*)(smc + OFF_BIAS + tid * 4) = bias[tid];

    uint2* Ah = (uint2*)(smc + OFF_AHI);
    uint2* Al = (uint2*)(smc + OFF_ALO);
    uint2* Bh = (uint2*)(smc + OFF_BHI);
    uint2* Bl = (uint2*)(smc + OFF_BLO);

    // ---- stage A: 128 rows x 128 k ----
    {
        int k4 = tid & 31;
        int ms = tid >> 5;          // 0..7
        int kk = k4 * 4;
        const float* basep = (kk < 64) ? (meanp + kk) : (xp + kk - 64);
#pragma unroll 4
        for (int m = ms; m < 128; m += 8) {
            int node = node0 + m;
            float4 v = make_float4(0.f, 0.f, 0.f, 0.f);
            if (node < NN) v = *(const float4*)(basep + node * D);
            uint32_t h01, h23, l01, l23;
            hilo_pack(v, h01, h23, l01, l23);
            int w2 = (m * ASTRIDE_W + (kk >> 1)) >> 1;
            Ah[w2] = make_uint2(h01, h23);
            Al[w2] = make_uint2(l01, l23);
        }
    }
    // ---- stage B: 64 rows x 128 k ----
    {
        int k4 = tid & 31;
        int js = tid >> 5;
        int kk = k4 * 4;
        const float* basep = (kk < 64) ? (Wl + kk) : (Wr + kk - 64);
#pragma unroll 4
        for (int j = js; j < 64; j += 8) {
            float4 v = *(const float4*)(basep + j * 64);
            uint32_t h01, h23, l01, l23;
            hilo_pack(v, h01, h23, l01, l23);
            int w2 = (j * ASTRIDE_W + (kk >> 1)) >> 1;
            Bh[w2] = make_uint2(h01, h23);
            Bl[w2] = make_uint2(l01, l23);
        }
    }
    __syncthreads();

    // ---- main loop via ldmatrix: warp w -> rows [w*16, w*16+16) ----
    uint32_t sAh = (uint32_t)__cvta_generic_to_shared(smc + OFF_AHI);
    uint32_t sAl = (uint32_t)__cvta_generic_to_shared(smc + OFF_ALO);
    uint32_t sBh = (uint32_t)__cvta_generic_to_shared(smc + OFF_BHI);
    uint32_t sBl = (uint32_t)__cvta_generic_to_shared(smc + OFF_BLO);

    uint32_t aoff = (uint32_t)(((wid * 16 + (lane & 15)) * ASTRIDE_W + (lane >> 4) * 4) * 4);
    uint32_t boff = (uint32_t)(((((lane >> 3) >> 1) * 8 + (lane & 7)) * ASTRIDE_W
                               + ((lane >> 3) & 1) * 4) * 4);

    float acc[8][4];
#pragma unroll
    for (int nt = 0; nt < 8; nt++)
#pragma unroll
        for (int r = 0; r < 4; r++) acc[nt][r] = 0.f;

    int r4 = lane >> 2;
    int c4 = lane & 3;

#pragma unroll
    for (int ks = 0; ks < 8; ks++) {
        uint32_t kb = (uint32_t)(ks * 32);      // 8 words per ks

        uint32_t bh[8][2], bl[8][2];
#pragma unroll
        for (int ntp = 0; ntp < 4; ntp++) {
            uint32_t ob = boff + (uint32_t)(ntp * 16 * ASTRIDE_W * 4) + kb;
            LDSM4(bh[2 * ntp][0], bh[2 * ntp][1], bh[2 * ntp + 1][0], bh[2 * ntp + 1][1],
                  sBh + ob);
            LDSM4(bl[2 * ntp][0], bl[2 * ntp][1], bl[2 * ntp + 1][0], bl[2 * ntp + 1][1],
                  sBl + ob);
        }
        uint32_t oa = aoff + kb;
        uint32_t ah0, ah1, ah2, ah3, al0, al1, al2, al3;
        LDSM4(ah0, ah1, ah2, ah3, sAh + oa);
        LDSM4(al0, al1, al2, al3, sAl + oa);
#pragma unroll
        for (int nt = 0; nt < 8; nt++) {
            mma16816(acc[nt], ah0, ah1, ah2, ah3, bh[nt][0], bh[nt][1]);
            mma16816(acc[nt], ah0, ah1, ah2, ah3, bl[nt][0], bl[nt][1]);
            mma16816(acc[nt], al0, al1, al2, al3, bh[nt][0], bh[nt][1]);
        }
    }

    // ---- epilogue ----
    const float* bsm = (const float*)(smc + OFF_BIAS);
    int row0 = node0 + wid * 16 + r4;
#pragma unroll
    for (int nt = 0; nt < 8; nt++) {
        int col = nt * 8 + 2 * c4;
        float bx = bsm[col], by = bsm[col + 1];
        float f0 = acc[nt][0] + bx, f1 = acc[nt][1] + by;
        float f2 = acc[nt][2] + bx, f3 = acc[nt][3] + by;
        if (do_relu) {
            f0 = fmaxf(f0, 0.f); f1 = fmaxf(f1, 0.f);
            f2 = fmaxf(f2, 0.f); f3 = fmaxf(f3, 0.f);
        }
        if (row0 < NN)     *(float2*)(outp + row0 * D + col)       = make_float2(f0, f1);
        if (row0 + 8 < NN) *(float2*)(outp + (row0 + 8) * D + col) = make_float2(f2, f3);
    }
}

// ---------------- launch -----------------------------------------------------
extern "C" void kernel_launch(void* const* d_in, const int* in_sizes, int n_in,
                              void* d_out, int out_size)
{
    const float* x   = (const float*)d_in[0];
    const void*  ei  = d_in[1];
    const float* W1l = (const float*)d_in[2];
    const float* b1l = (const float*)d_in[3];
    const float* W1r = (const float*)d_in[4];
    const float* W2l = (const float*)d_in[5];
    const float* b2l = (const float*)d_in[6];
    const float* W2r = (const float*)d_in[7];
    float* out = (float*)d_out;

    cudaFuncSetAttribute(k_gemm_mma, cudaFuncAttributeMaxDynamicSharedMemorySize, GEMM_SMEM);

    float* d_mean; cudaGetSymbolAddress((void**)&d_mean, g_meanbuf);
    float* d_h;    cudaGetSymbolAddress((void**)&d_h, g_h);

    int hist_grid = (NE / HIST_ILP + 255) / 256;   // 977
    int fill_grid = (NE / FILL_ILP + 255) / 256;   // 1954

    k_hist<<<hist_grid, 256>>>(ei);
    k_scan<<<SCAN_NB, SCAN_B>>>();
    k_fill<<<fill_grid, 256>>>(ei);

    int agg_grid = (NN * 16) / 256;          // 6250, exact — no partial warps
    int grid     = (NN + 127) / 128;         // 782

    k_agg     <<<agg_grid, 256>>>(x, d_mean);
    k_gemm_mma<<<grid, 256, GEMM_SMEM>>>(d_mean, x, W1l, W1r, b1l, d_h, 1);
    k_agg     <<<agg_grid, 256>>>(d_h, d_mean);
    k_gemm_mma<<<grid, 256, GEMM_SMEM>>>(d_mean, d_h, W2l, W2r, b2l, out, 0);
}

// round 15
// speedup vs baseline: 1.0528x; 1.0035x over previous
#include <cuda_runtime.h>
#include <cuda_bf16.h>
#include <math.h>
#include <stdint.h>

#define NN 100000
#define NE 1000000
#define D  64

// ---------------- scratch ----------------------------------------------------
__device__ int      g_deg[NN];        // invariant: all-zero at kernel_launch entry/exit
__device__ int      g_off[NN + 1];
__device__ int      g_rank[NE];
__device__ int      g_adj[NE];
__device__ float    g_h[NN * D];
__device__ float    g_meanbuf[NN * D];
__device__ unsigned g_scanpub[128];   // invariant: all-zero at entry/exit (fill clears)

#define SCAN_B 1024
#define SCAN_NB ((NN + SCAN_B - 1) / SCAN_B)   // 98

// ---------------- edge dtype handling ---------------------------------------
__device__ __forceinline__ int edge_at(const void* ei, int idx, int is64) {
    if (is64) return (int)((const long long*)ei)[idx];
    return ((const int*)ei)[idx];
}

// Per-warp dtype probe: sample first 128 int64 words. If the buffer is int32
// (x64-disabled JAX), high words are the next edge values — nonzero with
// prob 1-1e-5 each, so all-128-zero is impossible in practice.
__device__ __forceinline__ int probe_is64(const void* ei) {
    const long long* e64 = (const long long*)ei;
    int lane = threadIdx.x & 31;
    int bad = 0;
#pragma unroll
    for (int u = 0; u < 4; u++) {
        long long v = e64[lane + 32 * u];
        if (v < 0 || v >= NN) bad = 1;
    }
    return __ballot_sync(0xFFFFFFFFu, bad) == 0u;
}

// ---------------- CSR build --------------------------------------------------
#define HIST_ILP 4
__global__ void k_hist(const void* __restrict__ ei) {
    int gid = blockIdx.x * blockDim.x + threadIdx.x;
    int stride = gridDim.x * blockDim.x;
    int is64 = probe_is64(ei);
    int dst[HIST_ILP];
#pragma unroll
    for (int u = 0; u < HIST_ILP; u++) {
        int e = gid + u * stride;
        dst[u] = (e < NE) ? edge_at(ei, NE + e, is64) : -1;
    }
    int rk[HIST_ILP];
#pragma unroll
    for (int u = 0; u < HIST_ILP; u++)
        rk[u] = ((unsigned)dst[u] < NN) ? atomicAdd(&g_deg[dst[u]], 1) : -1;
#pragma unroll
    for (int u = 0; u < HIST_ILP; u++) {
        int e = gid + u * stride;
        if (rk[u] >= 0) g_rank[e] = rk[u];
    }
}

// single-pass exclusive scan with decoupled lookback; restores g_deg=0 and
// writes the g_off[NN] sentinel.
__global__ __launch_bounds__(SCAN_B) void k_scan(void) {
    __shared__ int wsum[32];
    __shared__ int s_base;
    int tid = threadIdx.x, lane = tid & 31, w = tid >> 5;
    int i = blockIdx.x * SCAN_B + tid;
    int v = (i < NN) ? g_deg[i] : 0;
    int p = v;
#pragma unroll
    for (int st = 1; st < 32; st <<= 1) {
        int t = __shfl_up_sync(0xFFFFFFFFu, p, st);
        if (lane >= st) p += t;
    }
    if (lane == 31) wsum[w] = p;
    if (tid == 0) s_base = 0;
    __syncthreads();
    if (w == 0) {
        int s = wsum[lane];
#pragma unroll
        for (int st = 1; st < 32; st <<= 1) {
            int t = __shfl_up_sync(0xFFFFFFFFu, s, st);
            if (lane >= st) s += t;
        }
        wsum[lane] = s;
    }
    __syncthreads();
    int wbase = (w > 0) ? wsum[w - 1] : 0;
    int incl = wbase + p;
    if (tid == SCAN_B - 1)
        ((volatile unsigned*)g_scanpub)[blockIdx.x] = 0x80000000u | (unsigned)incl;
    if (tid < blockIdx.x) {
        unsigned u;
        do { u = ((volatile unsigned*)g_scanpub)[tid]; } while (!(u & 0x80000000u));
        atomicAdd(&s_base, (int)(u & 0x7FFFFFFFu));
    }
    __syncthreads();
    if (i < NN) {
        g_off[i] = s_base + incl - v;
        g_deg[i] = 0;                       // restore invariant
        if (i == NN - 1) g_off[NN] = s_base + incl;   // sentinel (= NE)
    }
}

// atomic-free fill: slot = off[dst] + rank[e]. Also clears scanpub flags.
#define FILL_ILP 2
__global__ void k_fill(const void* __restrict__ ei) {
    int gid = blockIdx.x * blockDim.x + threadIdx.x;
    int stride = gridDim.x * blockDim.x;
    if (gid < SCAN_NB) g_scanpub[gid] = 0u;   // restore invariant for next call
    int is64 = probe_is64(ei);
    int src[FILL_ILP], dst[FILL_ILP], rk[FILL_ILP];
#pragma unroll
    for (int u = 0; u < FILL_ILP; u++) {
        int e = gid + u * stride;
        if (e < NE) {
            src[u] = edge_at(ei, e, is64);
            dst[u] = edge_at(ei, NE + e, is64);
            rk[u]  = g_rank[e];
        } else { src[u] = -1; dst[u] = -1; rk[u] = 0; }
    }
    int base[FILL_ILP];
#pragma unroll
    for (int u = 0; u < FILL_ILP; u++)
        base[u] = ((unsigned)dst[u] < NN) ? __ldg(&g_off[dst[u]]) : -1;
#pragma unroll
    for (int u = 0; u < FILL_ILP; u++)
        if (base[u] >= 0 && (unsigned)src[u] < NN)
            g_adj[base[u] + rk[u]] = src[u];
}

// ---------------- mean aggregation: half-warp/node, shfl-bcast, f32x2 -------
// Each lane loads ONE coalesced index per 16-neighbor chunk; shfl(width=16)
// broadcasts it; rows are loaded as double2 (two 64-bit reg pairs) and
// accumulated with packed add.rn.f32x2 — 2 adds instead of 4 FADD.
__global__ void k_agg(const float* __restrict__ feat, float* __restrict__ outm) {
    int hw = (blockIdx.x * blockDim.x + threadIdx.x) >> 4;  // node id (grid exact)
    int c  = threadIdx.x & 15;                              // 16B lane
    unsigned mask = 0xFFFFu << (threadIdx.x & 16);          // own half-warp lanes
    int o = g_off[hw];
    int d = g_off[hw + 1] - o;
    const double2* f2 = (const double2*)feat;               // 16 double2 per row
    unsigned long long a0 = 0ULL, a1 = 0ULL;                // packed (f32,f32) pairs
    for (int t = 0; t < d; t += 16) {
        int idx = (t + c < d) ? g_adj[o + t + c] : 0;
#pragma unroll
        for (int u = 0; u < 16; u++) {
            int nb = __shfl_sync(mask, idx, u, 16);
            if (t + u < d) {
                double2 v = f2[nb * 16 + c];
                unsigned long long vx = __double_as_longlong(v.x);
                unsigned long long vy = __double_as_longlong(v.y);
                asm("add.rn.f32x2 %0, %0, %1;" : "+l"(a0) : "l"(vx));
                asm("add.rn.f32x2 %0, %0, %1;" : "+l"(a1) : "l"(vy));
            }
        }
    }
    float inv = 1.0f / (float)max(d, 1);
    unsigned long long iv;
    asm("mov.b64 %0, {%1, %1};" : "=l"(iv) : "r"(__float_as_uint(inv)));
    asm("mul.rn.f32x2 %0, %0, %1;" : "+l"(a0) : "l"(iv));
    asm("mul.rn.f32x2 %0, %0, %1;" : "+l"(a1) : "l"(iv));
    double2 outv;
    outv.x = __longlong_as_double(a0);
    outv.y = __longlong_as_double(a1);
    ((double2*)outm)[hw * 16 + c] = outv;
}

// ---------------- HMMA bf16 3-pass GEMM, 256 threads, ldmatrix ---------------
#define ASTRIDE_W 68            // words per smem row (136 bf16: 128 + 8 pad)
#define OFF_BIAS 0
#define OFF_AHI  256
#define OFF_ALO  (OFF_AHI + 128 * ASTRIDE_W * 4)
#define OFF_BHI  (OFF_ALO + 128 * ASTRIDE_W * 4)
#define OFF_BLO  (OFF_BHI + 64 * ASTRIDE_W * 4)
#define GEMM_SMEM (OFF_BLO + 64 * ASTRIDE_W * 4)    // 104704 B

__device__ __forceinline__ void hilo_pack(float4 v, uint32_t& h01, uint32_t& h23,
                                          uint32_t& l01, uint32_t& l23) {
    uint32_t u0 = __float_as_uint(v.x), u1 = __float_as_uint(v.y);
    uint32_t u2 = __float_as_uint(v.z), u3 = __float_as_uint(v.w);
    float h0 = __uint_as_float(u0 & 0xFFFF0000u);
    float h1 = __uint_as_float(u1 & 0xFFFF0000u);
    float h2 = __uint_as_float(u2 & 0xFFFF0000u);
    float h3 = __uint_as_float(u3 & 0xFFFF0000u);
    h01 = (u0 >> 16) | (u1 & 0xFFFF0000u);
    h23 = (u2 >> 16) | (u3 & 0xFFFF0000u);
    float l0 = v.x - h0, l1 = v.y - h1, l2 = v.z - h2, l3 = v.w - h3;
    asm("cvt.rn.bf16x2.f32 %0, %1, %2;" : "=r"(l01) : "f"(l1), "f"(l0));
    asm("cvt.rn.bf16x2.f32 %0, %1, %2;" : "=r"(l23) : "f"(l3), "f"(l2));
}

__device__ __forceinline__ void mma16816(float* d, uint32_t a0, uint32_t a1,
                                         uint32_t a2, uint32_t a3,
                                         uint32_t b0, uint32_t b1) {
    asm volatile(
        "mma.sync.aligned.m16n8k16.row.col.f32.bf16.bf16.f32 "
        "{%0,%1,%2,%3}, {%4,%5,%6,%7}, {%8,%9}, {%0,%1,%2,%3};"
        : "+f"(d[0]), "+f"(d[1]), "+f"(d[2]), "+f"(d[3])
        : "r"(a0), "r"(a1), "r"(a2), "r"(a3), "r"(b0), "r"(b1));
}

#define LDSM4(r0, r1, r2, r3, addr) \
    asm volatile("ldmatrix.sync.aligned.m8n8.x4.shared.b16 {%0,%1,%2,%3}, [%4];" \
                 : "=r"(r0), "=r"(r1), "=r"(r2), "=r"(r3) : "r"(addr))

__global__ __launch_bounds__(256) void k_gemm_mma(
    const float* __restrict__ meanp, const float* __restrict__ xp,
    const float* __restrict__ Wl, const float* __restrict__ Wr,
    const float* __restrict__ bias, float* __restrict__ outp, int do_relu)
{
    extern __shared__ char smc[];
    int tid = threadIdx.x;
    int wid = tid >> 5, lane = tid & 31;
    int node0 = blockIdx.x * 128;

    if (tid < 64) *(float*)(smc + OFF_BIAS + tid * 4) = bias[tid];

    uint2* Ah = (uint2*)(smc + OFF_AHI);
    uint2* Al = (uint2*)(smc + OFF_ALO);
    uint2* Bh = (uint2*)(smc + OFF_BHI);
    uint2* Bl = (uint2*)(smc + OFF_BLO);

    // ---- stage A: 128 rows x 128 k ----
    {
        int k4 = tid & 31;
        int ms = tid >> 5;          // 0..7
        int kk = k4 * 4;
        const float* basep = (kk < 64) ? (meanp + kk) : (xp + kk - 64);
#pragma unroll 4
        for (int m = ms; m < 128; m += 8) {
            int node = node0 + m;
            float4 v = make_float4(0.f, 0.f, 0.f, 0.f);
            if (node < NN) v = *(const float4*)(basep + node * D);
            uint32_t h01, h23, l01, l23;
            hilo_pack(v, h01, h23, l01, l23);
            int w2 = (m * ASTRIDE_W + (kk >> 1)) >> 1;
            Ah[w2] = make_uint2(h01, h23);
            Al[w2] = make_uint2(l01, l23);
        }
    }
    // ---- stage B: 64 rows x 128 k ----
    {
        int k4 = tid & 31;
        int js = tid >> 5;
        int kk = k4 * 4;
        const float* basep = (kk < 64) ? (Wl + kk) : (Wr + kk - 64);
#pragma unroll 4
        for (int j = js; j < 64; j += 8) {
            float4 v = *(const float4*)(basep + j * 64);
            uint32_t h01, h23, l01, l23;
            hilo_pack(v, h01, h23, l01, l23);
            int w2 = (j * ASTRIDE_W + (kk >> 1)) >> 1;
            Bh[w2] = make_uint2(h01, h23);
            Bl[w2] = make_uint2(l01, l23);
        }
    }
    __syncthreads();

    // ---- main loop via ldmatrix: warp w -> rows [w*16, w*16+16) ----
    uint32_t sAh = (uint32_t)__cvta_generic_to_shared(smc + OFF_AHI);
    uint32_t sAl = (uint32_t)__cvta_generic_to_shared(smc + OFF_ALO);
    uint32_t sBh = (uint32_t)__cvta_generic_to_shared(smc + OFF_BHI);
    uint32_t sBl = (uint32_t)__cvta_generic_to_shared(smc + OFF_BLO);

    uint32_t aoff = (uint32_t)(((wid * 16 + (lane & 15)) * ASTRIDE_W + (lane >> 4) * 4) * 4);
    uint32_t boff = (uint32_t)(((((lane >> 3) >> 1) * 8 + (lane & 7)) * ASTRIDE_W
                               + ((lane >> 3) & 1) * 4) * 4);

    float acc[8][4];
#pragma unroll
    for (int nt = 0; nt < 8; nt++)
#pragma unroll
        for (int r = 0; r < 4; r++) acc[nt][r] = 0.f;

    int r4 = lane >> 2;
    int c4 = lane & 3;

#pragma unroll
    for (int ks = 0; ks < 8; ks++) {
        uint32_t kb = (uint32_t)(ks * 32);      // 8 words per ks

        uint32_t bh[8][2], bl[8][2];
#pragma unroll
        for (int ntp = 0; ntp < 4; ntp++) {
            uint32_t ob = boff + (uint32_t)(ntp * 16 * ASTRIDE_W * 4) + kb;
            LDSM4(bh[2 * ntp][0], bh[2 * ntp][1], bh[2 * ntp + 1][0], bh[2 * ntp + 1][1],
                  sBh + ob);
            LDSM4(bl[2 * ntp][0], bl[2 * ntp][1], bl[2 * ntp + 1][0], bl[2 * ntp + 1][1],
                  sBl + ob);
        }
        uint32_t oa = aoff + kb;
        uint32_t ah0, ah1, ah2, ah3, al0, al1, al2, al3;
        LDSM4(ah0, ah1, ah2, ah3, sAh + oa);
        LDSM4(al0, al1, al2, al3, sAl + oa);
#pragma unroll
        for (int nt = 0; nt < 8; nt++) {
            mma16816(acc[nt], ah0, ah1, ah2, ah3, bh[nt][0], bh[nt][1]);
            mma16816(acc[nt], ah0, ah1, ah2, ah3, bl[nt][0], bl[nt][1]);
            mma16816(acc[nt], al0, al1, al2, al3, bh[nt][0], bh[nt][1]);
        }
    }

    // ---- epilogue ----
    const float* bsm = (const float*)(smc + OFF_BIAS);
    int row0 = node0 + wid * 16 + r4;
#pragma unroll
    for (int nt = 0; nt < 8; nt++) {
        int col = nt * 8 + 2 * c4;
        float bx = bsm[col], by = bsm[col + 1];
        float f0 = acc[nt][0] + bx, f1 = acc[nt][1] + by;
        float f2 = acc[nt][2] + bx, f3 = acc[nt][3] + by;
        if (do_relu) {
            f0 = fmaxf(f0, 0.f); f1 = fmaxf(f1, 0.f);
            f2 = fmaxf(f2, 0.f); f3 = fmaxf(f3, 0.f);
        }
        if (row0 < NN)     *(float2*)(outp + row0 * D + col)       = make_float2(f0, f1);
        if (row0 + 8 < NN) *(float2*)(outp + (row0 + 8) * D + col) = make_float2(f2, f3);
    }
}

// ---------------- launch -----------------------------------------------------
extern "C" void kernel_launch(void* const* d_in, const int* in_sizes, int n_in,
                              void* d_out, int out_size)
{
    const float* x   = (const float*)d_in[0];
    const void*  ei  = d_in[1];
    const float* W1l = (const float*)d_in[2];
    const float* b1l = (const float*)d_in[3];
    const float* W1r = (const float*)d_in[4];
    const float* W2l = (const float*)d_in[5];
    const float* b2l = (const float*)d_in[6];
    const float* W2r = (const float*)d_in[7];
    float* out = (float*)d_out;

    cudaFuncSetAttribute(k_gemm_mma, cudaFuncAttributeMaxDynamicSharedMemorySize, GEMM_SMEM);

    float* d_mean; cudaGetSymbolAddress((void**)&d_mean, g_meanbuf);
    float* d_h;    cudaGetSymbolAddress((void**)&d_h, g_h);

    int hist_grid = (NE / HIST_ILP + 255) / 256;   // 977
    int fill_grid = (NE / FILL_ILP + 255) / 256;   // 1954

    k_hist<<<hist_grid, 256>>>(ei);
    k_scan<<<SCAN_NB, SCAN_B>>>();
    k_fill<<<fill_grid, 256>>>(ei);

    int agg_grid = (NN * 16) / 256;          // 6250, exact — no partial warps
    int grid     = (NN + 127) / 128;         // 782

    k_agg     <<<agg_grid, 256>>>(x, d_mean);
    k_gemm_mma<<<grid, 256, GEMM_SMEM>>>(d_mean, x, W1l, W1r, b1l, d_h, 1);
    k_agg     <<<agg_grid, 256>>>(d_h, d_mean);
    k_gemm_mma<<<grid, 256, GEMM_SMEM>>>(d_mean, d_h, W2l, W2r, b2l, out, 0);
}

// round 16
// speedup vs baseline: 1.0533x; 1.0005x over previous
#include <cuda_runtime.h>
#include <cuda_bf16.h>
#include <math.h>
#include <stdint.h>

#define NN 100000
#define NE 1000000
#define D  64

// ---------------- scratch ----------------------------------------------------
__device__ int      g_deg[NN];        // invariant: all-zero at kernel_launch entry/exit
__device__ int      g_off[NN + 1];
__device__ int      g_rank[NE];
__device__ int      g_adj[NE];
__device__ float    g_h[NN * D];
__device__ float    g_meanbuf[NN * D];
__device__ unsigned g_scanpub[128];   // invariant: all-zero at entry/exit (fill clears)

#define SCAN_B 1024
#define SCAN_NB ((NN + SCAN_B - 1) / SCAN_B)   // 98

// ---------------- edge dtype handling ---------------------------------------
__device__ __forceinline__ int edge_at(const void* ei, int idx, int is64) {
    if (is64) return (int)((const long long*)ei)[idx];
    return ((const int*)ei)[idx];
}

// Per-warp dtype probe: sample first 128 int64 words. If the buffer is int32
// (x64-disabled JAX), high words are the next edge values — nonzero with
// prob 1-1e-5 each, so all-128-zero is impossible in practice.
__device__ __forceinline__ int probe_is64(const void* ei) {
    const long long* e64 = (const long long*)ei;
    int lane = threadIdx.x & 31;
    int bad = 0;
#pragma unroll
    for (int u = 0; u < 4; u++) {
        long long v = e64[lane + 32 * u];
        if (v < 0 || v >= NN) bad = 1;
    }
    return __ballot_sync(0xFFFFFFFFu, bad) == 0u;
}

// ---------------- CSR build --------------------------------------------------
#define HIST_ILP 4
__global__ void k_hist(const void* __restrict__ ei) {
    int gid = blockIdx.x * blockDim.x + threadIdx.x;
    int stride = gridDim.x * blockDim.x;
    int is64 = probe_is64(ei);
    int dst[HIST_ILP];
#pragma unroll
    for (int u = 0; u < HIST_ILP; u++) {
        int e = gid + u * stride;
        dst[u] = (e < NE) ? edge_at(ei, NE + e, is64) : -1;
    }
    int rk[HIST_ILP];
#pragma unroll
    for (int u = 0; u < HIST_ILP; u++)
        rk[u] = ((unsigned)dst[u] < NN) ? atomicAdd(&g_deg[dst[u]], 1) : -1;
#pragma unroll
    for (int u = 0; u < HIST_ILP; u++) {
        int e = gid + u * stride;
        if (rk[u] >= 0) g_rank[e] = rk[u];
    }
}

// single-pass exclusive scan with decoupled lookback; restores g_deg=0 and
// writes the g_off[NN] sentinel.
__global__ __launch_bounds__(SCAN_B) void k_scan(void) {
    __shared__ int wsum[32];
    __shared__ int s_base;
    int tid = threadIdx.x, lane = tid & 31, w = tid >> 5;
    int i = blockIdx.x * SCAN_B + tid;
    int v = (i < NN) ? g_deg[i] : 0;
    int p = v;
#pragma unroll
    for (int st = 1; st < 32; st <<= 1) {
        int t = __shfl_up_sync(0xFFFFFFFFu, p, st);
        if (lane >= st) p += t;
    }
    if (lane == 31) wsum[w] = p;
    if (tid == 0) s_base = 0;
    __syncthreads();
    if (w == 0) {
        int s = wsum[lane];
#pragma unroll
        for (int st = 1; st < 32; st <<= 1) {
            int t = __shfl_up_sync(0xFFFFFFFFu, s, st);
            if (lane >= st) s += t;
        }
        wsum[lane] = s;
    }
    __syncthreads();
    int wbase = (w > 0) ? wsum[w - 1] : 0;
    int incl = wbase + p;
    if (tid == SCAN_B - 1)
        ((volatile unsigned*)g_scanpub)[blockIdx.x] = 0x80000000u | (unsigned)incl;
    if (tid < blockIdx.x) {
        unsigned u;
        do { u = ((volatile unsigned*)g_scanpub)[tid]; } while (!(u & 0x80000000u));
        atomicAdd(&s_base, (int)(u & 0x7FFFFFFFu));
    }
    __syncthreads();
    if (i < NN) {
        g_off[i] = s_base + incl - v;
        g_deg[i] = 0;                       // restore invariant
        if (i == NN - 1) g_off[NN] = s_base + incl;   // sentinel (= NE)
    }
}

// atomic-free fill: slot = off[dst] + rank[e]. Also clears scanpub flags.
#define FILL_ILP 2
__global__ void k_fill(const void* __restrict__ ei) {
    int gid = blockIdx.x * blockDim.x + threadIdx.x;
    int stride = gridDim.x * blockDim.x;
    if (gid < SCAN_NB) g_scanpub[gid] = 0u;   // restore invariant for next call
    int is64 = probe_is64(ei);
    int src[FILL_ILP], dst[FILL_ILP], rk[FILL_ILP];
#pragma unroll
    for (int u = 0; u < FILL_ILP; u++) {
        int e = gid + u * stride;
        if (e < NE) {
            src[u] = edge_at(ei, e, is64);
            dst[u] = edge_at(ei, NE + e, is64);
            rk[u]  = g_rank[e];
        } else { src[u] = -1; dst[u] = -1; rk[u] = 0; }
    }
    int base[FILL_ILP];
#pragma unroll
    for (int u = 0; u < FILL_ILP; u++)
        base[u] = ((unsigned)dst[u] < NN) ? __ldg(&g_off[dst[u]]) : -1;
#pragma unroll
    for (int u = 0; u < FILL_ILP; u++)
        if (base[u] >= 0 && (unsigned)src[u] < NN)
            g_adj[base[u] + rk[u]] = src[u];
}

// ---------------- mean aggregation: 8 lanes/node, 32B/lane, f32x2 -----------
// Each lane owns two float4 chunks (c and c+8) of the 64-float row. One lane
// loads ONE coalesced index per 8-neighbor chunk; shfl(width=8) broadcasts;
// two independent LDG.128 per neighbor per lane (MLP 16 per chunk).
__global__ void k_agg(const float* __restrict__ feat, float* __restrict__ outm) {
    int node = (blockIdx.x * blockDim.x + threadIdx.x) >> 3;  // node id (grid exact)
    int c    = threadIdx.x & 7;                               // chunk lane
    unsigned mask = 0xFFu << (threadIdx.x & 24);              // own 8-lane segment
    int o = g_off[node];
    int d = g_off[node + 1] - o;
    const double2* f2 = (const double2*)feat;                 // 16 double2 per row
    unsigned long long a0 = 0ULL, a1 = 0ULL;                  // chunk c
    unsigned long long a2 = 0ULL, a3 = 0ULL;                  // chunk c+8
    for (int t = 0; t < d; t += 8) {
        int idx = (t + c < d) ? g_adj[o + t + c] : 0;
#pragma unroll
        for (int u = 0; u < 8; u++) {
            int nb = __shfl_sync(mask, idx, u, 8);
            if (t + u < d) {
                double2 v0 = f2[nb * 16 + c];
                double2 v1 = f2[nb * 16 + c + 8];
                unsigned long long x0 = __double_as_longlong(v0.x);
                unsigned long long y0 = __double_as_longlong(v0.y);
                unsigned long long x1 = __double_as_longlong(v1.x);
                unsigned long long y1 = __double_as_longlong(v1.y);
                asm("add.rn.f32x2 %0, %0, %1;" : "+l"(a0) : "l"(x0));
                asm("add.rn.f32x2 %0, %0, %1;" : "+l"(a1) : "l"(y0));
                asm("add.rn.f32x2 %0, %0, %1;" : "+l"(a2) : "l"(x1));
                asm("add.rn.f32x2 %0, %0, %1;" : "+l"(a3) : "l"(y1));
            }
        }
    }
    float inv = 1.0f / (float)max(d, 1);
    unsigned long long iv;
    asm("mov.b64 %0, {%1, %1};" : "=l"(iv) : "r"(__float_as_uint(inv)));
    asm("mul.rn.f32x2 %0, %0, %1;" : "+l"(a0) : "l"(iv));
    asm("mul.rn.f32x2 %0, %0, %1;" : "+l"(a1) : "l"(iv));
    asm("mul.rn.f32x2 %0, %0, %1;" : "+l"(a2) : "l"(iv));
    asm("mul.rn.f32x2 %0, %0, %1;" : "+l"(a3) : "l"(iv));
    double2 o0, o1;
    o0.x = __longlong_as_double(a0); o0.y = __longlong_as_double(a1);
    o1.x = __longlong_as_double(a2); o1.y = __longlong_as_double(a3);
    ((double2*)outm)[node * 16 + c]     = o0;
    ((double2*)outm)[node * 16 + c + 8] = o1;
}

// ---------------- HMMA bf16 3-pass GEMM, 256 threads, ldmatrix ---------------
#define ASTRIDE_W 68            // words per smem row (136 bf16: 128 + 8 pad)
#define OFF_BIAS 0
#define OFF_AHI  256
#define OFF_ALO  (OFF_AHI + 128 * ASTRIDE_W * 4)
#define OFF_BHI  (OFF_ALO + 128 * ASTRIDE_W * 4)
#define OFF_BLO  (OFF_BHI + 64 * ASTRIDE_W * 4)
#define GEMM_SMEM (OFF_BLO + 64 * ASTRIDE_W * 4)    // 104704 B

__device__ __forceinline__ void hilo_pack(float4 v, uint32_t& h01, uint32_t& h23,
                                          uint32_t& l01, uint32_t& l23) {
    uint32_t u0 = __float_as_uint(v.x), u1 = __float_as_uint(v.y);
    uint32_t u2 = __float_as_uint(v.z), u3 = __float_as_uint(v.w);
    float h0 = __uint_as_float(u0 & 0xFFFF0000u);
    float h1 = __uint_as_float(u1 & 0xFFFF0000u);
    float h2 = __uint_as_float(u2 & 0xFFFF0000u);
    float h3 = __uint_as_float(u3 & 0xFFFF0000u);
    h01 = (u0 >> 16) | (u1 & 0xFFFF0000u);
    h23 = (u2 >> 16) | (u3 & 0xFFFF0000u);
    float l0 = v.x - h0, l1 = v.y - h1, l2 = v.z - h2, l3 = v.w - h3;
    asm("cvt.rn.bf16x2.f32 %0, %1, %2;" : "=r"(l01) : "f"(l1), "f"(l0));
    asm("cvt.rn.bf16x2.f32 %0, %1, %2;" : "=r"(l23) : "f"(l3), "f"(l2));
}

__device__ __forceinline__ void mma16816(float* d, uint32_t a0, uint32_t a1,
                                         uint32_t a2, uint32_t a3,
                                         uint32_t b0, uint32_t b1) {
    asm volatile(
        "mma.sync.aligned.m16n8k16.row.col.f32.bf16.bf16.f32 "
        "{%0,%1,%2,%3}, {%4,%5,%6,%7}, {%8,%9}, {%0,%1,%2,%3};"
        : "+f"(d[0]), "+f"(d[1]), "+f"(d[2]), "+f"(d[3])
        : "r"(a0), "r"(a1), "r"(a2), "r"(a3), "r"(b0), "r"(b1));
}

#define LDSM4(r0, r1, r2, r3, addr) \
    asm volatile("ldmatrix.sync.aligned.m8n8.x4.shared.b16 {%0,%1,%2,%3}, [%4];" \
                 : "=r"(r0), "=r"(r1), "=r"(r2), "=r"(r3) : "r"(addr))

__global__ __launch_bounds__(256) void k_gemm_mma(
    const float* __restrict__ meanp, const float* __restrict__ xp,
    const float* __restrict__ Wl, const float* __restrict__ Wr,
    const float* __restrict__ bias, float* __restrict__ outp, int do_relu)
{
    extern __shared__ char smc[];
    int tid = threadIdx.x;
    int wid = tid >> 5, lane = tid & 31;
    int node0 = blockIdx.x * 128;

    if (tid < 64) *(float*)(smc + OFF_BIAS + tid * 4) = bias[tid];

    uint2* Ah = (uint2*)(smc + OFF_AHI);
    uint2* Al = (uint2*)(smc + OFF_ALO);
    uint2* Bh = (uint2*)(smc + OFF_BHI);
    uint2* Bl = (uint2*)(smc + OFF_BLO);

    // ---- stage A: 128 rows x 128 k ----
    {
        int k4 = tid & 31;
        int ms = tid >> 5;          // 0..7
        int kk = k4 * 4;
        const float* basep = (kk < 64) ? (meanp + kk) : (xp + kk - 64);
#pragma unroll 4
        for (int m = ms; m < 128; m += 8) {
            int node = node0 + m;
            float4 v = make_float4(0.f, 0.f, 0.f, 0.f);
            if (node < NN) v = *(const float4*)(basep + node * D);
            uint32_t h01, h23, l01, l23;
            hilo_pack(v, h01, h23, l01, l23);
            int w2 = (m * ASTRIDE_W + (kk >> 1)) >> 1;
            Ah[w2] = make_uint2(h01, h23);
            Al[w2] = make_uint2(l01, l23);
        }
    }
    // ---- stage B: 64 rows x 128 k ----
    {
        int k4 = tid & 31;
        int js = tid >> 5;
        int kk = k4 * 4;
        const float* basep = (kk < 64) ? (Wl + kk) : (Wr + kk - 64);
#pragma unroll 4
        for (int j = js; j < 64; j += 8) {
            float4 v = *(const float4*)(basep + j * 64);
            uint32_t h01, h23, l01, l23;
            hilo_pack(v, h01, h23, l01, l23);
            int w2 = (j * ASTRIDE_W + (kk >> 1)) >> 1;
            Bh[w2] = make_uint2(h01, h23);
            Bl[w2] = make_uint2(l01, l23);
        }
    }
    __syncthreads();

    // ---- main loop via ldmatrix: warp w -> rows [w*16, w*16+16) ----
    uint32_t sAh = (uint32_t)__cvta_generic_to_shared(smc + OFF_AHI);
    uint32_t sAl = (uint32_t)__cvta_generic_to_shared(smc + OFF_ALO);
    uint32_t sBh = (uint32_t)__cvta_generic_to_shared(smc + OFF_BHI);
    uint32_t sBl = (uint32_t)__cvta_generic_to_shared(smc + OFF_BLO);

    uint32_t aoff = (uint32_t)(((wid * 16 + (lane & 15)) * ASTRIDE_W + (lane >> 4) * 4) * 4);
    uint32_t boff = (uint32_t)(((((lane >> 3) >> 1) * 8 + (lane & 7)) * ASTRIDE_W
                               + ((lane >> 3) & 1) * 4) * 4);

    float acc[8][4];
#pragma unroll
    for (int nt = 0; nt < 8; nt++)
#pragma unroll
        for (int r = 0; r < 4; r++) acc[nt][r] = 0.f;

    int r4 = lane >> 2;
    int c4 = lane & 3;

#pragma unroll
    for (int ks = 0; ks < 8; ks++) {
        uint32_t kb = (uint32_t)(ks * 32);      // 8 words per ks

        uint32_t bh[8][2], bl[8][2];
#pragma unroll
        for (int ntp = 0; ntp < 4; ntp++) {
            uint32_t ob = boff + (uint32_t)(ntp * 16 * ASTRIDE_W * 4) + kb;
            LDSM4(bh[2 * ntp][0], bh[2 * ntp][1], bh[2 * ntp + 1][0], bh[2 * ntp + 1][1],
                  sBh + ob);
            LDSM4(bl[2 * ntp][0], bl[2 * ntp][1], bl[2 * ntp + 1][0], bl[2 * ntp + 1][1],
                  sBl + ob);
        }
        uint32_t oa = aoff + kb;
        uint32_t ah0, ah1, ah2, ah3, al0, al1, al2, al3;
        LDSM4(ah0, ah1, ah2, ah3, sAh + oa);
        LDSM4(al0, al1, al2, al3, sAl + oa);
#pragma unroll
        for (int nt = 0; nt < 8; nt++) {
            mma16816(acc[nt], ah0, ah1, ah2, ah3, bh[nt][0], bh[nt][1]);
            mma16816(acc[nt], ah0, ah1, ah2, ah3, bl[nt][0], bl[nt][1]);
            mma16816(acc[nt], al0, al1, al2, al3, bh[nt][0], bh[nt][1]);
        }
    }

    // ---- epilogue ----
    const float* bsm = (const float*)(smc + OFF_BIAS);
    int row0 = node0 + wid * 16 + r4;
#pragma unroll
    for (int nt = 0; nt < 8; nt++) {
        int col = nt * 8 + 2 * c4;
        float bx = bsm[col], by = bsm[col + 1];
        float f0 = acc[nt][0] + bx, f1 = acc[nt][1] + by;
        float f2 = acc[nt][2] + bx, f3 = acc[nt][3] + by;
        if (do_relu) {
            f0 = fmaxf(f0, 0.f); f1 = fmaxf(f1, 0.f);
            f2 = fmaxf(f2, 0.f); f3 = fmaxf(f3, 0.f);
        }
        if (row0 < NN)     *(float2*)(outp + row0 * D + col)       = make_float2(f0, f1);
        if (row0 + 8 < NN) *(float2*)(outp + (row0 + 8) * D + col) = make_float2(f2, f3);
    }
}

// ---------------- launch -----------------------------------------------------
extern "C" void kernel_launch(void* const* d_in, const int* in_sizes, int n_in,
                              void* d_out, int out_size)
{
    const float* x   = (const float*)d_in[0];
    const void*  ei  = d_in[1];
    const float* W1l = (const float*)d_in[2];
    const float* b1l = (const float*)d_in[3];
    const float* W1r = (const float*)d_in[4];
    const float* W2l = (const float*)d_in[5];
    const float* b2l = (const float*)d_in[6];
    const float* W2r = (const float*)d_in[7];
    float* out = (float*)d_out;

    cudaFuncSetAttribute(k_gemm_mma, cudaFuncAttributeMaxDynamicSharedMemorySize, GEMM_SMEM);

    float* d_mean; cudaGetSymbolAddress((void**)&d_mean, g_meanbuf);
    float* d_h;    cudaGetSymbolAddress((void**)&d_h, g_h);

    int hist_grid = (NE / HIST_ILP + 255) / 256;   // 977
    int fill_grid = (NE / FILL_ILP + 255) / 256;   // 1954

    k_hist<<<hist_grid, 256>>>(ei);
    k_scan<<<SCAN_NB, SCAN_B>>>();
    k_fill<<<fill_grid, 256>>>(ei);

    int agg_grid = (NN * 8) / 256;           // 3125, exact — no partial segments
    int grid     = (NN + 127) / 128;         // 782

    k_agg     <<<agg_grid, 256>>>(x, d_mean);
    k_gemm_mma<<<grid, 256, GEMM_SMEM>>>(d_mean, x, W1l, W1r, b1l, d_h, 1);
    k_agg     <<<agg_grid, 256>>>(d_h, d_mean);
    k_gemm_mma<<<grid, 256, GEMM_SMEM>>>(d_mean, d_h, W2l, W2r, b2l, out, 0);
}